// round 1
// baseline (speedup 1.0000x reference)
#include <cuda_runtime.h>
#include <cstdint>
#include <cstdio>

// ---------------- problem constants ----------------
#define BB 8
#define NN 2048
#define CIN 64
#define C2 128          // 2*CIN
#define NK 32           // neighbors
#define KDIM 4096       // C2*NK
#define NPTS (BB*NN)    // 16384
#define COUT 128

// ---------------- device scratch (static, no allocs) ----------------
__device__ float g_A[(size_t)NPTS * KDIM];      // 256 MB: per-point feats2, tf32-rounded
__device__ float g_featT[(size_t)BB * NN * CIN]; // feature transposed [b][n][c]
__device__ float g_xT[(size_t)BB * NN * 3];      // coords transposed [b][n][d]
__device__ float g_cwT[(size_t)KDIM * COUT];     // conv_w transposed [k][o], tf32-rounded

__device__ __forceinline__ float tf32r(float x) {
    uint32_t u;
    asm("cvt.rna.tf32.f32 %0, %1;" : "=r"(u) : "f"(x));
    return __uint_as_float(u);
}

// ---------------- kernel 0: transposes + weight conversion ----------------
__global__ void prep_kernel(const float* __restrict__ x,
                            const float* __restrict__ feat,
                            const float* __restrict__ cw) {
    const int stride = gridDim.x * blockDim.x;
    const int tid = blockIdx.x * blockDim.x + threadIdx.x;

    // feature [B, C, N] -> featT [B, N, C]
    for (int e = tid; e < BB * CIN * NN; e += stride) {
        int b = e / (CIN * NN);
        int r = e - b * (CIN * NN);
        int c = r / NN;
        int n = r - c * NN;
        g_featT[((size_t)b * NN + n) * CIN + c] = feat[e];
    }
    // x [B, 3, N] -> xT [B, N, 3]
    for (int e = tid; e < BB * 3 * NN; e += stride) {
        int b = e / (3 * NN);
        int r = e - b * (3 * NN);
        int d = r / NN;
        int n = r - d * NN;
        g_xT[((size_t)b * NN + n) * 3 + d] = x[e];
    }
    // conv_w [O, K] -> cwT [K, O], rounded to tf32
    for (int e = tid; e < COUT * KDIM; e += stride) {
        int o = e >> 12;           // / 4096
        int k = e & (KDIM - 1);
        g_cwT[(size_t)k * COUT + o] = tf32r(cw[e]);
    }
}

// ---------------- kernel 1: per-point feats2 = shuffle(concat(gather, mlp(RFF))) @ perm ----------------
__global__ __launch_bounds__(128) void point_kernel(
    const int*   __restrict__ nidx,
    const float* __restrict__ Brff,   // [7,32]
    const float* __restrict__ kern,   // [3,32]
    const float* __restrict__ mw,     // [64,64]
    const float* __restrict__ mb)     // [64]
{
    const int p = blockIdx.x;        // point id 0..16383
    const int b = p >> 11;           // / 2048
    const int t = threadIdx.x;       // 0..127

    __shared__ float s_crd[32][3];
    __shared__ float s_rel[32][3];
    __shared__ float s_dis[32];
    __shared__ int   s_idx[32];
    __shared__ float s_perm[32][33];
    __shared__ float s_xf[32][65];   // [k][m], m<32: sin, m>=32: cos
    __shared__ float s_F[128][33];   // shuffled channel order
    __shared__ float s_mw[64][65];
    __shared__ float s_br[7][32];
    __shared__ float s_kn[3][32];
    __shared__ float s_mb[64];

    // stage constants
    for (int e = t; e < 224; e += 128) s_br[e >> 5][e & 31] = Brff[e];
    for (int e = t; e < 96;  e += 128) s_kn[e >> 5][e & 31] = kern[e];
    if (t < 64) s_mb[t] = mb[t];
    for (int e = t; e < 4096; e += 128) s_mw[e >> 6][e & 63] = mw[e];

    if (t < 32) s_idx[t] = nidx[p * NK + t];
    __syncthreads();

    if (t < 32) {
        int nb = s_idx[t];
        const float* cp = g_xT + ((size_t)b * NN + nb) * 3;
        s_crd[t][0] = cp[0]; s_crd[t][1] = cp[1]; s_crd[t][2] = cp[2];
    }
    __syncthreads();
    if (t < 32) {
        float r0 = s_crd[t][0] - s_crd[0][0];
        float r1 = s_crd[t][1] - s_crd[0][1];
        float r2 = s_crd[t][2] - s_crd[0][2];
        s_rel[t][0] = r0; s_rel[t][1] = r1; s_rel[t][2] = r2;
        s_dis[t] = sqrtf(r0 * r0 + r1 * r1 + r2 * r2);
    }
    __syncthreads();

    // ---- perm = relu(x_rel @ kernels + one_pad) ----
    for (int e = t; e < 1024; e += 128) {
        int i = e >> 5, j = e & 31;
        float v = s_rel[i][0] * s_kn[0][j] + s_rel[i][1] * s_kn[1][j] + s_rel[i][2] * s_kn[2][j];
        if (e == 0) v += 1.0f;
        s_perm[i][j] = fmaxf(v, 0.0f);
    }
    __syncthreads();

    // ---- topkmax: per-column normalize, square, normalize, threshold ----
    if (t < 32) {
        const int j = t;
        float s1 = 0.f;
        #pragma unroll
        for (int i = 0; i < 32; i++) s1 += s_perm[i][j];
        float r1 = 1.0f / (s1 + 1e-6f);
        float s2 = 0.f;
        #pragma unroll
        for (int i = 0; i < 32; i++) {
            float v = s_perm[i][j] * r1;
            v *= v;
            s_perm[i][j] = v;
            s2 += v;
        }
        float r2 = 1.0f / (s2 + 1e-6f);
        #pragma unroll
        for (int i = 0; i < 32; i++) {
            float v = s_perm[i][j] * r2;
            s_perm[i][j] = (v > 0.1f) ? v : 0.0f;
        }
    }

    // ---- RFF: sin/cos(2*pi * pos . B_rff) ----
    for (int e = t; e < 1024; e += 128) {
        int k = e >> 5, m = e & 31;
        float arg = s_crd[0][0] * s_br[0][m] + s_crd[0][1] * s_br[1][m] + s_crd[0][2] * s_br[2][m]
                  + s_rel[k][0] * s_br[3][m] + s_rel[k][1] * s_br[4][m] + s_rel[k][2] * s_br[5][m]
                  + s_dis[k]    * s_br[6][m];
        arg *= 6.283185307179586f;
        float sv, cv;
        sincosf(arg, &sv, &cv);
        s_xf[k][m]      = sv;
        s_xf[k][32 + m] = cv;
    }
    __syncthreads();

    // ---- mlp: out[c][k] = mb[c] + sum_m mw[c][m] * xf[k][m]; store shuffled ----
    {
        const int ct = (t >> 3) * 4;   // 0..60
        const int kt = (t & 7) * 4;    // 0..28
        float acc[4][4];
        #pragma unroll
        for (int ci = 0; ci < 4; ci++) {
            float bv = s_mb[ct + ci];
            #pragma unroll
            for (int kj = 0; kj < 4; kj++) acc[ci][kj] = bv;
        }
        #pragma unroll
        for (int m = 0; m < 64; m++) {
            float wv[4], xv[4];
            #pragma unroll
            for (int ci = 0; ci < 4; ci++) wv[ci] = s_mw[ct + ci][m];
            #pragma unroll
            for (int kj = 0; kj < 4; kj++) xv[kj] = s_xf[kt + kj][m];
            #pragma unroll
            for (int ci = 0; ci < 4; ci++)
                #pragma unroll
                for (int kj = 0; kj < 4; kj++)
                    acc[ci][kj] += wv[ci] * xv[kj];
        }
        #pragma unroll
        for (int ci = 0; ci < 4; ci++) {
            int c  = ct + ci;                       // mlp channel, full channel = 64 + c
            int cs = (c & 31) * 4 + 2 + (c >> 5);   // shuffled index
            #pragma unroll
            for (int kj = 0; kj < 4; kj++) s_F[cs][kt + kj] = acc[ci][kj];
        }
    }

    // ---- gathered features (first 64 channels), shuffled ----
    for (int e = t; e < 2048; e += 128) {
        int c = e & 63, k = e >> 6;
        float v = g_featT[((size_t)b * NN + s_idx[k]) * CIN + c];
        s_F[(c & 31) * 4 + (c >> 5)][k] = v;
    }
    __syncthreads();

    // ---- feats2 = F @ perm, store tf32-rounded to g_A ----
    {
        const int ct = (t >> 3) * 8;   // 0..120
        const int jt = (t & 7) * 4;    // 0..28
        float acc[8][4];
        #pragma unroll
        for (int r = 0; r < 8; r++)
            #pragma unroll
            for (int s = 0; s < 4; s++) acc[r][s] = 0.f;

        #pragma unroll 8
        for (int i = 0; i < 32; i++) {
            float fv[8], pv[4];
            #pragma unroll
            for (int r = 0; r < 8; r++) fv[r] = s_F[ct + r][i];
            #pragma unroll
            for (int s = 0; s < 4; s++) pv[s] = s_perm[i][jt + s];
            #pragma unroll
            for (int r = 0; r < 8; r++)
                #pragma unroll
                for (int s = 0; s < 4; s++) acc[r][s] += fv[r] * pv[s];
        }
        float* Ap = g_A + (size_t)p * KDIM;
        #pragma unroll
        for (int r = 0; r < 8; r++) {
            float4 v;
            v.x = tf32r(acc[r][0]); v.y = tf32r(acc[r][1]);
            v.z = tf32r(acc[r][2]); v.w = tf32r(acc[r][3]);
            *reinterpret_cast<float4*>(Ap + (ct + r) * 32 + jt) = v;
        }
    }
}

// ---------------- kernel 2: C[16384,128] = A @ cwT via mma.sync tf32 ----------------
// CTA tile 128(M) x 128(N), K-chunk 16, double-buffered smem.
// 8 warps, each 32(M) x 64(N): 2 m16 atoms x 8 n8 atoms.

#define KC 16
#define AS_LD 20
#define BS_LD 136
#define AS_BUF (128 * AS_LD)
#define BS_BUF (KC * BS_LD)

__device__ __forceinline__ void mma_tf32(float& c0, float& c1, float& c2, float& c3,
                                         float a0, float a1, float a2, float a3,
                                         float b0, float b1) {
    asm volatile(
        "mma.sync.aligned.m16n8k8.row.col.f32.tf32.tf32.f32 "
        "{%0,%1,%2,%3},{%4,%5,%6,%7},{%8,%9},{%0,%1,%2,%3};"
        : "+f"(c0), "+f"(c1), "+f"(c2), "+f"(c3)
        : "r"(__float_as_uint(a0)), "r"(__float_as_uint(a1)),
          "r"(__float_as_uint(a2)), "r"(__float_as_uint(a3)),
          "r"(__float_as_uint(b0)), "r"(__float_as_uint(b1)));
}

__global__ __launch_bounds__(256, 1) void gemm_kernel(
    const float* __restrict__ bias, float* __restrict__ out)
{
    __shared__ float As[2 * AS_BUF];   // [buf][m][k], 20.5 KB
    __shared__ float Bs[2 * BS_BUF];   // [buf][k][n], 17.4 KB
    __shared__ float s_bias[COUT];

    const int t = threadIdx.x;
    const int p0 = blockIdx.x * 128;
    const int bb = p0 >> 11;
    const int n0 = p0 & (NN - 1);

    if (t < COUT) s_bias[t] = bias[t];

    // global->reg staging coords
    const int arow = t >> 2;            // 0..63 (+64)
    const int acol = (t & 3) * 4;       // 0..12
    const int brow = t >> 5;            // 0..7 (+8)
    const int bcol = (t & 31) * 4;      // 0..124

    const int lane = t & 31;
    const int wid  = t >> 5;
    const int grp  = lane >> 2;
    const int tig  = lane & 3;
    const int wm = (wid >> 1) * 32;     // 0,32,64,96
    const int wn = (wid & 1) * 64;      // 0,64

    float4 ra[2], rb[2];

    auto ldg = [&](int kc) {
        #pragma unroll
        for (int q = 0; q < 2; q++)
            ra[q] = *reinterpret_cast<const float4*>(
                g_A + (size_t)(p0 + arow + 64 * q) * KDIM + kc + acol);
        #pragma unroll
        for (int q = 0; q < 2; q++)
            rb[q] = *reinterpret_cast<const float4*>(
                g_cwT + (size_t)(kc + brow + 8 * q) * COUT + bcol);
    };
    auto sts = [&](int buf) {
        #pragma unroll
        for (int q = 0; q < 2; q++)
            *reinterpret_cast<float4*>(&As[buf * AS_BUF + (arow + 64 * q) * AS_LD + acol]) = ra[q];
        #pragma unroll
        for (int q = 0; q < 2; q++)
            *reinterpret_cast<float4*>(&Bs[buf * BS_BUF + (brow + 8 * q) * BS_LD + bcol]) = rb[q];
    };

    float c[2][8][4];
    #pragma unroll
    for (int ma = 0; ma < 2; ma++)
        #pragma unroll
        for (int nb = 0; nb < 8; nb++)
            #pragma unroll
            for (int r = 0; r < 4; r++) c[ma][nb][r] = 0.f;

    ldg(0);
    sts(0);
    __syncthreads();

    const int NIT = KDIM / KC;   // 256
    for (int kt = 0; kt < NIT; kt++) {
        const int cur = kt & 1;
        if (kt + 1 < NIT) ldg((kt + 1) * KC);

        #pragma unroll
        for (int ks = 0; ks < 2; ks++) {
            const int k0 = ks * 8;
            float a[2][4];
            #pragma unroll
            for (int ma = 0; ma < 2; ma++) {
                const int mbase = wm + ma * 16;
                const float* ap = &As[cur * AS_BUF];
                a[ma][0] = ap[(mbase + grp)     * AS_LD + k0 + tig];
                a[ma][1] = ap[(mbase + grp + 8) * AS_LD + k0 + tig];
                a[ma][2] = ap[(mbase + grp)     * AS_LD + k0 + tig + 4];
                a[ma][3] = ap[(mbase + grp + 8) * AS_LD + k0 + tig + 4];
            }
            #pragma unroll
            for (int nb = 0; nb < 8; nb++) {
                const float* bp = &Bs[cur * BS_BUF];
                float b0 = bp[(k0 + tig)     * BS_LD + wn + nb * 8 + grp];
                float b1 = bp[(k0 + tig + 4) * BS_LD + wn + nb * 8 + grp];
                #pragma unroll
                for (int ma = 0; ma < 2; ma++)
                    mma_tf32(c[ma][nb][0], c[ma][nb][1], c[ma][nb][2], c[ma][nb][3],
                             a[ma][0], a[ma][1], a[ma][2], a[ma][3], b0, b1);
            }
        }
        if (kt + 1 < NIT) sts(cur ^ 1);
        __syncthreads();
    }

    // epilogue: out[b][o][n] with p = b*2048 + n; o = gemm col, n = n0 + gemm row
    float* ob = out + (size_t)bb * COUT * NN;
    #pragma unroll
    for (int ma = 0; ma < 2; ma++) {
        const int m0 = wm + ma * 16 + grp;
        #pragma unroll
        for (int nb = 0; nb < 8; nb++) {
            const int col0 = wn + nb * 8 + tig * 2;
            const float bv0 = s_bias[col0], bv1 = s_bias[col0 + 1];
            ob[(size_t)col0       * NN + n0 + m0]     = c[ma][nb][0] + bv0;
            ob[(size_t)(col0 + 1) * NN + n0 + m0]     = c[ma][nb][1] + bv1;
            ob[(size_t)col0       * NN + n0 + m0 + 8] = c[ma][nb][2] + bv0;
            ob[(size_t)(col0 + 1) * NN + n0 + m0 + 8] = c[ma][nb][3] + bv1;
        }
    }
}

// ---------------- launch ----------------
extern "C" void kernel_launch(void* const* d_in, const int* in_sizes, int n_in,
                              void* d_out, int out_size) {
    const float* x       = (const float*)d_in[0];
    const float* feature = (const float*)d_in[1];
    const int*   nidx    = (const int*)  d_in[2];
    const float* Brff    = (const float*)d_in[3];
    const float* kern    = (const float*)d_in[4];
    const float* mw      = (const float*)d_in[5];
    const float* mb      = (const float*)d_in[6];
    const float* cw      = (const float*)d_in[7];
    const float* cb      = (const float*)d_in[8];
    float* out = (float*)d_out;

    prep_kernel<<<1024, 256>>>(x, feature, cw);
    point_kernel<<<NPTS, 128>>>(nidx, Brff, kern, mw, mb);
    gemm_kernel<<<NPTS / 128, 256>>>(cb, out);
}

// round 2
// speedup vs baseline: 1.2079x; 1.2079x over previous
#include <cuda_runtime.h>
#include <cstdint>

// ---------------- problem constants ----------------
#define BB 8
#define NN 2048
#define CIN 64
#define NK 32           // neighbors
#define KDIM 4096       // 2*CIN*NK
#define NPTS (BB*NN)    // 16384
#define COUT 128

// ---------------- device scratch (static, no allocs) ----------------
__device__ float g_A[(size_t)NPTS * KDIM];       // 256 MB: per-point feats2, tf32-rounded
__device__ float g_featT[(size_t)BB * NN * CIN]; // feature transposed [b][n][c]
__device__ float g_xT[(size_t)BB * NN * 3];      // coords transposed [b][n][d]
__device__ float g_cwT[(size_t)KDIM * COUT];     // conv_w transposed [k][o], tf32-rounded

__device__ __forceinline__ float tf32r(float x) {
    uint32_t u;
    asm("cvt.rna.tf32.f32 %0, %1;" : "=r"(u) : "f"(x));
    return __uint_as_float(u);
}

__device__ __forceinline__ void mma_tf32(float& c0, float& c1, float& c2, float& c3,
                                         float a0, float a1, float a2, float a3,
                                         float b0, float b1) {
    asm volatile(
        "mma.sync.aligned.m16n8k8.row.col.f32.tf32.tf32.f32 "
        "{%0,%1,%2,%3},{%4,%5,%6,%7},{%8,%9},{%0,%1,%2,%3};"
        : "+f"(c0), "+f"(c1), "+f"(c2), "+f"(c3)
        : "r"(__float_as_uint(a0)), "r"(__float_as_uint(a1)),
          "r"(__float_as_uint(a2)), "r"(__float_as_uint(a3)),
          "r"(__float_as_uint(b0)), "r"(__float_as_uint(b1)));
}

// ---------------- kernel 0: transposes + weight conversion ----------------
__global__ void prep_kernel(const float* __restrict__ x,
                            const float* __restrict__ feat,
                            const float* __restrict__ cw) {
    const int stride = gridDim.x * blockDim.x;
    const int tid = blockIdx.x * blockDim.x + threadIdx.x;

    for (int e = tid; e < BB * CIN * NN; e += stride) {
        int b = e / (CIN * NN);
        int r = e - b * (CIN * NN);
        int c = r / NN;
        int n = r - c * NN;
        g_featT[((size_t)b * NN + n) * CIN + c] = feat[e];
    }
    for (int e = tid; e < BB * 3 * NN; e += stride) {
        int b = e / (3 * NN);
        int r = e - b * (3 * NN);
        int d = r / NN;
        int n = r - d * NN;
        g_xT[((size_t)b * NN + n) * 3 + d] = x[e];
    }
    for (int e = tid; e < COUT * KDIM; e += stride) {
        int o = e >> 12;
        int k = e & (KDIM - 1);
        g_cwT[(size_t)k * COUT + o] = tf32r(cw[e]);
    }
}

// ---------------- kernel 1: per-point, tensor-core MLP + F@perm ----------------
// 1 CTA = 1 point, 128 threads = 4 warps.
// GEMM1 (mlp): out[64c][32k] = mw[64c][64m] @ xf[32k][64m]^T  (mma M=16/warp, A const in regs)
// GEMM2:       feats2[128][32] = F[128][32i] @ perm[32i][32j]
__global__ __launch_bounds__(128) void point_kernel(
    const int*   __restrict__ nidx,
    const float* __restrict__ Brff,   // [7,32]
    const float* __restrict__ kern,   // [3,32]
    const float* __restrict__ mw,     // [64,64]
    const float* __restrict__ mb)     // [64]
{
    const int p = blockIdx.x;
    const int b = p >> 11;
    const int t = threadIdx.x;
    const int lane = t & 31;
    const int w = t >> 5;             // warp 0..3
    const int grp = lane >> 2;        // 0..7
    const int tig = lane & 3;         // 0..3

    __shared__ float s_xf[32][68];    // [k][m], m<32 sin, m>=32 cos (pad 68: conflict-free frags)
    __shared__ float s_F[128][36];    // shuffled channels x neighbor
    __shared__ float s_perm[32][36];  // [i][j]
    __shared__ float s_br[7][32];
    __shared__ float s_kn[3][32];
    __shared__ float s_mb[64];
    __shared__ float s_rel[32][3];
    __shared__ float s_dis[32];
    __shared__ float s_c0[3];
    __shared__ int   s_idx[32];

    // ---- constant A fragments for GEMM1: mw rows [16w,16w+16), tf32-rounded, in regs ----
    float amw[8][4];
    {
        const int r0 = w * 16 + grp;
        #pragma unroll
        for (int ks = 0; ks < 8; ks++) {
            const int m0 = ks * 8;
            amw[ks][0] = tf32r(mw[r0 * 64 + m0 + tig]);
            amw[ks][1] = tf32r(mw[(r0 + 8) * 64 + m0 + tig]);
            amw[ks][2] = tf32r(mw[r0 * 64 + m0 + tig + 4]);
            amw[ks][3] = tf32r(mw[(r0 + 8) * 64 + m0 + tig + 4]);
        }
    }

    // ---- stage small constants ----
    for (int e = t; e < 224; e += 128) s_br[e >> 5][e & 31] = Brff[e];
    if (t < 96) s_kn[t >> 5][t & 31] = kern[t];
    if (t < 64) s_mb[t] = mb[t];
    if (t < 32) s_idx[t] = nidx[p * NK + t];
    __syncthreads();

    // ---- warp0: neighbor coords -> rel, dis (register shuffle for neighbor 0) ----
    float cx = 0.f, cy = 0.f, cz = 0.f;
    if (t < 32) {
        const float* cp = g_xT + ((size_t)b * NN + s_idx[t]) * 3;
        cx = cp[0]; cy = cp[1]; cz = cp[2];
    }

    // ---- feature gather -> s_F (shuffled rows 0,1 mod 4), overlapped with coords ----
    #pragma unroll
    for (int it = 0; it < 16; it++) {
        int e = t + it * 128;
        int k = e >> 6, c = e & 63;
        float v = g_featT[((size_t)b * NN + s_idx[k]) * CIN + c];
        s_F[(c & 31) * 4 + (c >> 5)][k] = tf32r(v);
    }

    if (t < 32) {
        float c0x = __shfl_sync(0xffffffffu, cx, 0);
        float c0y = __shfl_sync(0xffffffffu, cy, 0);
        float c0z = __shfl_sync(0xffffffffu, cz, 0);
        float rx = cx - c0x, ry = cy - c0y, rz = cz - c0z;
        s_rel[t][0] = rx; s_rel[t][1] = ry; s_rel[t][2] = rz;
        s_dis[t] = sqrtf(rx * rx + ry * ry + rz * rz);
        if (t == 0) { s_c0[0] = c0x; s_c0[1] = c0y; s_c0[2] = c0z; }
    }
    __syncthreads();

    // ---- perm = relu(x_rel @ kernels + one_pad) ----
    #pragma unroll
    for (int it = 0; it < 8; it++) {
        int e = t + it * 128;
        int i = e >> 5, j = e & 31;
        float v = s_rel[i][0] * s_kn[0][j] + s_rel[i][1] * s_kn[1][j] + s_rel[i][2] * s_kn[2][j];
        if (e == 0) v += 1.0f;
        s_perm[i][j] = fmaxf(v, 0.0f);
    }

    // ---- RFF: sin/cos(2*pi * pos . B_rff), tf32-rounded ----
    const float c0x = s_c0[0], c0y = s_c0[1], c0z = s_c0[2];
    #pragma unroll
    for (int it = 0; it < 8; it++) {
        int e = t + it * 128;
        int k = e >> 5, m = e & 31;
        float arg = c0x * s_br[0][m] + c0y * s_br[1][m] + c0z * s_br[2][m]
                  + s_rel[k][0] * s_br[3][m] + s_rel[k][1] * s_br[4][m]
                  + s_rel[k][2] * s_br[5][m] + s_dis[k] * s_br[6][m];
        arg *= 6.283185307179586f;
        float sv, cv;
        __sincosf(arg, &sv, &cv);
        s_xf[k][m]      = tf32r(sv);
        s_xf[k][32 + m] = tf32r(cv);
    }
    __syncthreads();

    // ---- warp0: topkmax over columns (conflict-free: addr = i*36 + lane) ----
    if (t < 32) {
        const int j = t;
        float s1 = 0.f;
        #pragma unroll
        for (int i = 0; i < 32; i++) s1 += s_perm[i][j];
        float r1 = 1.0f / (s1 + 1e-6f);
        float s2 = 0.f;
        #pragma unroll
        for (int i = 0; i < 32; i++) {
            float v = s_perm[i][j] * r1;
            v *= v;
            s_perm[i][j] = v;
            s2 += v;
        }
        float r2 = 1.0f / (s2 + 1e-6f);
        #pragma unroll
        for (int i = 0; i < 32; i++) {
            float v = s_perm[i][j] * r2;
            s_perm[i][j] = (v > 0.1f) ? tf32r(v) : 0.0f;
        }
    }

    // ---- GEMM1 (tensor cores): mlp out rows [16w,16w+16), bias in accumulator ----
    {
        float acc[4][4];
        const float bv0 = s_mb[w * 16 + grp];
        const float bv1 = s_mb[w * 16 + grp + 8];
        #pragma unroll
        for (int nt = 0; nt < 4; nt++) {
            acc[nt][0] = bv0; acc[nt][1] = bv0;
            acc[nt][2] = bv1; acc[nt][3] = bv1;
        }
        #pragma unroll
        for (int ks = 0; ks < 8; ks++) {
            const int m0 = ks * 8;
            #pragma unroll
            for (int nt = 0; nt < 4; nt++) {
                float b0 = s_xf[nt * 8 + grp][m0 + tig];
                float b1 = s_xf[nt * 8 + grp][m0 + tig + 4];
                mma_tf32(acc[nt][0], acc[nt][1], acc[nt][2], acc[nt][3],
                         amw[ks][0], amw[ks][1], amw[ks][2], amw[ks][3], b0, b1);
            }
        }
        // store shuffled (mlp channel c -> full channel 64+c -> row (c&31)*4+2+(c>>5))
        const int r0 = w * 16 + grp, r1 = r0 + 8;
        const int cs0 = (r0 & 31) * 4 + 2 + (r0 >> 5);
        const int cs1 = (r1 & 31) * 4 + 2 + (r1 >> 5);
        #pragma unroll
        for (int nt = 0; nt < 4; nt++) {
            const int k = nt * 8 + tig * 2;
            float2 v0 = make_float2(tf32r(acc[nt][0]), tf32r(acc[nt][1]));
            float2 v1 = make_float2(tf32r(acc[nt][2]), tf32r(acc[nt][3]));
            *reinterpret_cast<float2*>(&s_F[cs0][k]) = v0;
            *reinterpret_cast<float2*>(&s_F[cs1][k]) = v1;
        }
    }
    __syncthreads();

    // ---- GEMM2 (tensor cores): feats2 = F @ perm, rows [32w, 32w+32) ----
    {
        float acc[2][4][4];
        #pragma unroll
        for (int mt = 0; mt < 2; mt++)
            #pragma unroll
            for (int nt = 0; nt < 4; nt++)
                #pragma unroll
                for (int r = 0; r < 4; r++) acc[mt][nt][r] = 0.f;

        #pragma unroll
        for (int ks = 0; ks < 4; ks++) {
            const int i0 = ks * 8;
            float a[2][4];
            #pragma unroll
            for (int mt = 0; mt < 2; mt++) {
                const int rb = w * 32 + mt * 16;
                a[mt][0] = s_F[rb + grp][i0 + tig];
                a[mt][1] = s_F[rb + grp + 8][i0 + tig];
                a[mt][2] = s_F[rb + grp][i0 + tig + 4];
                a[mt][3] = s_F[rb + grp + 8][i0 + tig + 4];
            }
            #pragma unroll
            for (int nt = 0; nt < 4; nt++) {
                float b0 = s_perm[i0 + tig][nt * 8 + grp];
                float b1 = s_perm[i0 + tig + 4][nt * 8 + grp];
                #pragma unroll
                for (int mt = 0; mt < 2; mt++)
                    mma_tf32(acc[mt][nt][0], acc[mt][nt][1], acc[mt][nt][2], acc[mt][nt][3],
                             a[mt][0], a[mt][1], a[mt][2], a[mt][3], b0, b1);
            }
        }

        float* Ap = g_A + (size_t)p * KDIM;
        #pragma unroll
        for (int mt = 0; mt < 2; mt++) {
            const int r = w * 32 + mt * 16 + grp;
            #pragma unroll
            for (int nt = 0; nt < 4; nt++) {
                const int j = nt * 8 + tig * 2;
                float2 v0 = make_float2(tf32r(acc[mt][nt][0]), tf32r(acc[mt][nt][1]));
                float2 v1 = make_float2(tf32r(acc[mt][nt][2]), tf32r(acc[mt][nt][3]));
                *reinterpret_cast<float2*>(&Ap[(size_t)r * 32 + j]) = v0;
                *reinterpret_cast<float2*>(&Ap[(size_t)(r + 8) * 32 + j]) = v1;
            }
        }
    }
}

// ---------------- kernel 2: C[16384,128] = A @ cwT via mma.sync tf32 ----------------
#define KC 16
#define AS_LD 20
#define BS_LD 136
#define AS_BUF (128 * AS_LD)
#define BS_BUF (KC * BS_LD)

__global__ __launch_bounds__(256, 1) void gemm_kernel(
    const float* __restrict__ bias, float* __restrict__ out)
{
    __shared__ float As[2 * AS_BUF];
    __shared__ float Bs[2 * BS_BUF];
    __shared__ float s_bias[COUT];

    const int t = threadIdx.x;
    const int p0 = blockIdx.x * 128;
    const int bb = p0 >> 11;
    const int n0 = p0 & (NN - 1);

    if (t < COUT) s_bias[t] = bias[t];

    const int arow = t >> 2;
    const int acol = (t & 3) * 4;
    const int brow = t >> 5;
    const int bcol = (t & 31) * 4;

    const int lane = t & 31;
    const int wid  = t >> 5;
    const int grp  = lane >> 2;
    const int tig  = lane & 3;
    const int wm = (wid >> 1) * 32;
    const int wn = (wid & 1) * 64;

    float4 ra[2], rb[2];

    auto ldg = [&](int kc) {
        #pragma unroll
        for (int q = 0; q < 2; q++)
            ra[q] = *reinterpret_cast<const float4*>(
                g_A + (size_t)(p0 + arow + 64 * q) * KDIM + kc + acol);
        #pragma unroll
        for (int q = 0; q < 2; q++)
            rb[q] = *reinterpret_cast<const float4*>(
                g_cwT + (size_t)(kc + brow + 8 * q) * COUT + bcol);
    };
    auto sts = [&](int buf) {
        #pragma unroll
        for (int q = 0; q < 2; q++)
            *reinterpret_cast<float4*>(&As[buf * AS_BUF + (arow + 64 * q) * AS_LD + acol]) = ra[q];
        #pragma unroll
        for (int q = 0; q < 2; q++)
            *reinterpret_cast<float4*>(&Bs[buf * BS_BUF + (brow + 8 * q) * BS_LD + bcol]) = rb[q];
    };

    float c[2][8][4];
    #pragma unroll
    for (int ma = 0; ma < 2; ma++)
        #pragma unroll
        for (int nb = 0; nb < 8; nb++)
            #pragma unroll
            for (int r = 0; r < 4; r++) c[ma][nb][r] = 0.f;

    ldg(0);
    sts(0);
    __syncthreads();

    const int NIT = KDIM / KC;
    for (int kt = 0; kt < NIT; kt++) {
        const int cur = kt & 1;
        if (kt + 1 < NIT) ldg((kt + 1) * KC);

        #pragma unroll
        for (int ks = 0; ks < 2; ks++) {
            const int k0 = ks * 8;
            float a[2][4];
            #pragma unroll
            for (int ma = 0; ma < 2; ma++) {
                const int mbase = wm + ma * 16;
                const float* ap = &As[cur * AS_BUF];
                a[ma][0] = ap[(mbase + grp)     * AS_LD + k0 + tig];
                a[ma][1] = ap[(mbase + grp + 8) * AS_LD + k0 + tig];
                a[ma][2] = ap[(mbase + grp)     * AS_LD + k0 + tig + 4];
                a[ma][3] = ap[(mbase + grp + 8) * AS_LD + k0 + tig + 4];
            }
            #pragma unroll
            for (int nb = 0; nb < 8; nb++) {
                const float* bp = &Bs[cur * BS_BUF];
                float b0 = bp[(k0 + tig)     * BS_LD + wn + nb * 8 + grp];
                float b1 = bp[(k0 + tig + 4) * BS_LD + wn + nb * 8 + grp];
                #pragma unroll
                for (int ma = 0; ma < 2; ma++)
                    mma_tf32(c[ma][nb][0], c[ma][nb][1], c[ma][nb][2], c[ma][nb][3],
                             a[ma][0], a[ma][1], a[ma][2], a[ma][3], b0, b1);
            }
        }
        if (kt + 1 < NIT) sts(cur ^ 1);
        __syncthreads();
    }

    float* ob = out + (size_t)bb * COUT * NN;
    #pragma unroll
    for (int ma = 0; ma < 2; ma++) {
        const int m0 = wm + ma * 16 + grp;
        #pragma unroll
        for (int nb = 0; nb < 8; nb++) {
            const int col0 = wn + nb * 8 + tig * 2;
            const float bv0 = s_bias[col0], bv1 = s_bias[col0 + 1];
            ob[(size_t)col0       * NN + n0 + m0]     = c[ma][nb][0] + bv0;
            ob[(size_t)(col0 + 1) * NN + n0 + m0]     = c[ma][nb][1] + bv1;
            ob[(size_t)col0       * NN + n0 + m0 + 8] = c[ma][nb][2] + bv0;
            ob[(size_t)(col0 + 1) * NN + n0 + m0 + 8] = c[ma][nb][3] + bv1;
        }
    }
}

// ---------------- launch ----------------
extern "C" void kernel_launch(void* const* d_in, const int* in_sizes, int n_in,
                              void* d_out, int out_size) {
    const float* x       = (const float*)d_in[0];
    const float* feature = (const float*)d_in[1];
    const int*   nidx    = (const int*)  d_in[2];
    const float* Brff    = (const float*)d_in[3];
    const float* kern    = (const float*)d_in[4];
    const float* mw      = (const float*)d_in[5];
    const float* mb      = (const float*)d_in[6];
    const float* cw      = (const float*)d_in[7];
    const float* cb      = (const float*)d_in[8];
    float* out = (float*)d_out;

    prep_kernel<<<1024, 256>>>(x, feature, cw);
    point_kernel<<<NPTS, 128>>>(nidx, Brff, kern, mw, mb);
    gemm_kernel<<<NPTS / 128, 256>>>(cb, out);
}

// round 3
// speedup vs baseline: 2.1007x; 1.7391x over previous
#include <cuda_runtime.h>
#include <cuda_fp16.h>
#include <cstdint>

// ---------------- problem constants ----------------
#define BB 8
#define NN 2048
#define CIN 64
#define NK 32
#define KDIM 4096
#define KD2  (KDIM/2)
#define NPTS (BB*NN)
#define COUT 128

// ---------------- device scratch (static, no allocs) ----------------
__device__ __half   g_Ah[(size_t)NPTS * KDIM];      // 128 MB, [p][k] fp16, k-pairs packed
__device__ float    g_featT[(size_t)BB * NN * CIN]; // feature transposed [b][n][c]
__device__ float    g_xT[(size_t)BB * NN * 3];      // coords transposed [b][n][d]
__device__ unsigned g_cwP[(size_t)KD2 * COUT];      // [k2][o] half2(w[o][2k2], w[o][2k2+1])

__device__ __forceinline__ unsigned pack2(float lo, float hi) {
    __half2 h = __floats2half2_rn(lo, hi);
    return *reinterpret_cast<unsigned*>(&h);
}

// m16n8k16 fp16 mma, f32 accumulate
__device__ __forceinline__ void mma_f16(float& c0, float& c1, float& c2, float& c3,
                                        unsigned a0, unsigned a1, unsigned a2, unsigned a3,
                                        unsigned b0, unsigned b1) {
    asm volatile(
        "mma.sync.aligned.m16n8k16.row.col.f32.f16.f16.f32 "
        "{%0,%1,%2,%3},{%4,%5,%6,%7},{%8,%9},{%0,%1,%2,%3};"
        : "+f"(c0), "+f"(c1), "+f"(c2), "+f"(c3)
        : "r"(a0), "r"(a1), "r"(a2), "r"(a3), "r"(b0), "r"(b1));
}

// ---------------- kernel 0: transposes + weight packing ----------------
__global__ void prep_kernel(const float* __restrict__ x,
                            const float* __restrict__ feat,
                            const float* __restrict__ cw) {
    const int stride = gridDim.x * blockDim.x;
    const int tid = blockIdx.x * blockDim.x + threadIdx.x;

    for (int e = tid; e < BB * CIN * NN; e += stride) {
        int b = e / (CIN * NN);
        int r = e - b * (CIN * NN);
        int c = r / NN;
        int n = r - c * NN;
        g_featT[((size_t)b * NN + n) * CIN + c] = feat[e];
    }
    for (int e = tid; e < BB * 3 * NN; e += stride) {
        int b = e / (3 * NN);
        int r = e - b * (3 * NN);
        int d = r / NN;
        int n = r - d * NN;
        g_xT[((size_t)b * NN + n) * 3 + d] = x[e];
    }
    // conv_w [O=128][K=4096] -> g_cwP[k2][o] packed half2 along k
    for (int e = tid; e < COUT * KD2; e += stride) {
        int o  = e >> 11;          // / 2048
        int k2 = e & (KD2 - 1);
        float2 v = *reinterpret_cast<const float2*>(cw + (size_t)o * KDIM + 2 * k2);
        g_cwP[(size_t)k2 * COUT + o] = pack2(v.x, v.y);
    }
}

// ---------------- kernel 1: per-point fp16 tensor-core MLP + F@perm ----------------
__global__ __launch_bounds__(128, 8) void point_kernel(
    const int*   __restrict__ nidx,
    const float* __restrict__ Brff,   // [7,32]
    const float* __restrict__ kern,   // [3,32]
    const float* __restrict__ mw,     // [64,64]
    const float* __restrict__ mb)     // [64]
{
    const int p = blockIdx.x;
    const int b = p >> 11;
    const int t = threadIdx.x;
    const int lane = t & 31;
    const int w = t >> 5;
    const int grp = lane >> 2;
    const int tig = lane & 3;

    __shared__ unsigned u_xf[32][36];  // [k][m2]: m pairs, m<32 sin block, m>=32 cos block
    __shared__ unsigned u_F[128][20];  // [shuffled ch][k2]: neighbor pairs
    __shared__ unsigned u_pT[32][20];  // [j][i2]: perm^T, i pairs
    __shared__ float s_br[7][32];
    __shared__ float s_rel[32][3];
    __shared__ float s_dis[32];
    __shared__ float s_c0[3];
    __shared__ int   s_idx[32];

    // constant A fragments for GEMM1 (mw rows [16w,16w+16)), fp16 packed
    unsigned amw[4][4];
    {
        const int r0 = w * 16 + grp;
        #pragma unroll
        for (int ks = 0; ks < 4; ks++) {
            const int m0 = ks * 16 + 2 * tig;
            float2 v0 = *reinterpret_cast<const float2*>(mw + r0 * 64 + m0);
            float2 v1 = *reinterpret_cast<const float2*>(mw + (r0 + 8) * 64 + m0);
            float2 v2 = *reinterpret_cast<const float2*>(mw + r0 * 64 + m0 + 8);
            float2 v3 = *reinterpret_cast<const float2*>(mw + (r0 + 8) * 64 + m0 + 8);
            amw[ks][0] = pack2(v0.x, v0.y);
            amw[ks][1] = pack2(v1.x, v1.y);
            amw[ks][2] = pack2(v2.x, v2.y);
            amw[ks][3] = pack2(v3.x, v3.y);
        }
    }
    const float bv0 = mb[w * 16 + grp];
    const float bv1 = mb[w * 16 + grp + 8];

    for (int e = t; e < 224; e += 128) s_br[e >> 5][e & 31] = Brff[e];
    if (t < 32) s_idx[t] = nidx[p * NK + t];
    __syncthreads();

    float cx = 0.f, cy = 0.f, cz = 0.f;
    if (t < 32) {
        const float* cp = g_xT + ((size_t)b * NN + s_idx[t]) * 3;
        cx = cp[0]; cy = cp[1]; cz = cp[2];
    }

    // feature gather -> u_F rows 0,1 mod 4 (shuffled), packed neighbor pairs
    #pragma unroll
    for (int it = 0; it < 8; it++) {
        int e = t + it * 128;
        int c = e & 63, k2 = e >> 6;
        float f0 = g_featT[((size_t)b * NN + s_idx[2 * k2])     * CIN + c];
        float f1 = g_featT[((size_t)b * NN + s_idx[2 * k2 + 1]) * CIN + c];
        u_F[(c & 31) * 4 + (c >> 5)][k2] = pack2(f0, f1);
    }

    if (t < 32) {
        float c0x = __shfl_sync(0xffffffffu, cx, 0);
        float c0y = __shfl_sync(0xffffffffu, cy, 0);
        float c0z = __shfl_sync(0xffffffffu, cz, 0);
        float rx = cx - c0x, ry = cy - c0y, rz = cz - c0z;
        s_rel[t][0] = rx; s_rel[t][1] = ry; s_rel[t][2] = rz;
        s_dis[t] = sqrtf(rx * rx + ry * ry + rz * rz);
        if (t == 0) { s_c0[0] = c0x; s_c0[1] = c0y; s_c0[2] = c0z; }
    }
    __syncthreads();

    // ---- RFF: sin/cos pairs -> u_xf ----
    const float c0x = s_c0[0], c0y = s_c0[1], c0z = s_c0[2];
    #pragma unroll
    for (int it = 0; it < 4; it++) {
        int e = t + it * 128;            // 512 pair-tasks
        int k = e >> 4, m2 = e & 15;
        float rx = s_rel[k][0], ry = s_rel[k][1], rz = s_rel[k][2], dd = s_dis[k];
        int m = 2 * m2;
        float a0 = (c0x * s_br[0][m] + c0y * s_br[1][m] + c0z * s_br[2][m]
                  + rx * s_br[3][m] + ry * s_br[4][m] + rz * s_br[5][m]
                  + dd * s_br[6][m]) * 6.283185307179586f;
        float a1 = (c0x * s_br[0][m+1] + c0y * s_br[1][m+1] + c0z * s_br[2][m+1]
                  + rx * s_br[3][m+1] + ry * s_br[4][m+1] + rz * s_br[5][m+1]
                  + dd * s_br[6][m+1]) * 6.283185307179586f;
        float s0, cv0, s1, cv1;
        __sincosf(a0, &s0, &cv0);
        __sincosf(a1, &s1, &cv1);
        u_xf[k][m2]      = pack2(s0, s1);
        u_xf[k][16 + m2] = pack2(cv0, cv1);
    }

    // ---- perm + topkmax, one column per thread, 3 recompute passes ----
    if (t < 32) {
        const int j = t;
        const float kx = kern[j], ky = kern[32 + j], kz = kern[64 + j];
        float s1 = 0.f;
        #pragma unroll
        for (int i = 0; i < 32; i++) {
            float v = s_rel[i][0] * kx + s_rel[i][1] * ky + s_rel[i][2] * kz;
            if (i == 0 && j == 0) v += 1.0f;
            s1 += fmaxf(v, 0.f);
        }
        float r1 = 1.0f / (s1 + 1e-6f);
        float s2 = 0.f;
        #pragma unroll
        for (int i = 0; i < 32; i++) {
            float v = s_rel[i][0] * kx + s_rel[i][1] * ky + s_rel[i][2] * kz;
            if (i == 0 && j == 0) v += 1.0f;
            v = fmaxf(v, 0.f) * r1;
            s2 += v * v;
        }
        float r2 = 1.0f / (s2 + 1e-6f);
        #pragma unroll
        for (int i2 = 0; i2 < 16; i2++) {
            float w0, w1;
            {
                int i = 2 * i2;
                float v = s_rel[i][0] * kx + s_rel[i][1] * ky + s_rel[i][2] * kz;
                if (i == 0 && j == 0) v += 1.0f;
                v = fmaxf(v, 0.f) * r1;
                v = v * v * r2;
                w0 = (v > 0.1f) ? v : 0.0f;
            }
            {
                int i = 2 * i2 + 1;
                float v = s_rel[i][0] * kx + s_rel[i][1] * ky + s_rel[i][2] * kz;
                v = fmaxf(v, 0.f) * r1;
                v = v * v * r2;
                w1 = (v > 0.1f) ? v : 0.0f;
            }
            u_pT[j][i2] = pack2(w0, w1);
        }
    }
    __syncthreads();

    // ---- GEMM1: mlp out rows [16w,16w+16), bias in accumulator ----
    {
        float acc[4][4];
        #pragma unroll
        for (int nt = 0; nt < 4; nt++) {
            acc[nt][0] = bv0; acc[nt][1] = bv0;
            acc[nt][2] = bv1; acc[nt][3] = bv1;
        }
        #pragma unroll
        for (int ks = 0; ks < 4; ks++) {
            const int kb = ks * 8;
            #pragma unroll
            for (int nt = 0; nt < 4; nt++) {
                unsigned b0 = u_xf[nt * 8 + grp][kb + tig];
                unsigned b1 = u_xf[nt * 8 + grp][kb + tig + 4];
                mma_f16(acc[nt][0], acc[nt][1], acc[nt][2], acc[nt][3],
                        amw[ks][0], amw[ks][1], amw[ks][2], amw[ks][3], b0, b1);
            }
        }
        const int r0 = w * 16 + grp, r1 = r0 + 8;
        const int cs0 = (r0 & 31) * 4 + 2 + (r0 >> 5);
        const int cs1 = (r1 & 31) * 4 + 2 + (r1 >> 5);
        #pragma unroll
        for (int nt = 0; nt < 4; nt++) {
            u_F[cs0][nt * 4 + tig] = pack2(acc[nt][0], acc[nt][1]);
            u_F[cs1][nt * 4 + tig] = pack2(acc[nt][2], acc[nt][3]);
        }
    }
    __syncthreads();

    // ---- GEMM2: feats2 = F @ perm, rows [32w, 32w+32) ----
    {
        float acc[2][4][4];
        #pragma unroll
        for (int mt = 0; mt < 2; mt++)
            #pragma unroll
            for (int nt = 0; nt < 4; nt++)
                #pragma unroll
                for (int r = 0; r < 4; r++) acc[mt][nt][r] = 0.f;

        #pragma unroll
        for (int ks = 0; ks < 2; ks++) {
            const int kb = ks * 8;
            unsigned a[2][4];
            #pragma unroll
            for (int mt = 0; mt < 2; mt++) {
                const int rb = w * 32 + mt * 16;
                a[mt][0] = u_F[rb + grp][kb + tig];
                a[mt][1] = u_F[rb + grp + 8][kb + tig];
                a[mt][2] = u_F[rb + grp][kb + tig + 4];
                a[mt][3] = u_F[rb + grp + 8][kb + tig + 4];
            }
            #pragma unroll
            for (int nt = 0; nt < 4; nt++) {
                unsigned b0 = u_pT[nt * 8 + grp][kb + tig];
                unsigned b1 = u_pT[nt * 8 + grp][kb + tig + 4];
                #pragma unroll
                for (int mt = 0; mt < 2; mt++)
                    mma_f16(acc[mt][nt][0], acc[mt][nt][1], acc[mt][nt][2], acc[mt][nt][3],
                            a[mt][0], a[mt][1], a[mt][2], a[mt][3], b0, b1);
            }
        }

        unsigned* Ap = reinterpret_cast<unsigned*>(g_Ah + (size_t)p * KDIM);
        #pragma unroll
        for (int mt = 0; mt < 2; mt++) {
            const int r = w * 32 + mt * 16 + grp;
            #pragma unroll
            for (int nt = 0; nt < 4; nt++) {
                Ap[r * 16 + nt * 4 + tig]       = pack2(acc[mt][nt][0], acc[mt][nt][1]);
                Ap[(r + 8) * 16 + nt * 4 + tig] = pack2(acc[mt][nt][2], acc[mt][nt][3]);
            }
        }
    }
}

// ---------------- kernel 2: C[16384,128] = A @ W via fp16 m16n8k16 ----------------
#define KC2 16   // uint (half2) columns per iteration = 32 k-values

__global__ __launch_bounds__(256, 1) void gemm_kernel(
    const float* __restrict__ bias, float* __restrict__ out)
{
    __shared__ unsigned Asu[2][128][20];
    __shared__ unsigned Bsu[2][16][132];
    __shared__ float s_bias[COUT];

    const int t = threadIdx.x;
    const int p0 = blockIdx.x * 128;
    const int bb = p0 >> 11;
    const int n0 = p0 & (NN - 1);

    if (t < COUT) s_bias[t] = bias[t];

    const int arow = t >> 1, ac = (t & 1) * 8;
    const int brow = t >> 4, bc = (t & 15) * 8;

    const int lane = t & 31;
    const int wid  = t >> 5;
    const int grp  = lane >> 2;
    const int tig  = lane & 3;
    const int wm = (wid >> 1) * 32;
    const int wn = (wid & 1) * 64;

    const unsigned* Ag = reinterpret_cast<const unsigned*>(g_Ah);
    uint4 ra0, ra1, rb0, rb1;

    auto ldg = [&](int k2c) {
        const unsigned* ap = Ag + (size_t)(p0 + arow) * KD2 + k2c + ac;
        ra0 = *reinterpret_cast<const uint4*>(ap);
        ra1 = *reinterpret_cast<const uint4*>(ap + 4);
        const unsigned* bp = g_cwP + (size_t)(k2c + brow) * COUT + bc;
        rb0 = *reinterpret_cast<const uint4*>(bp);
        rb1 = *reinterpret_cast<const uint4*>(bp + 4);
    };
    auto sts = [&](int buf) {
        *reinterpret_cast<uint4*>(&Asu[buf][arow][ac])     = ra0;
        *reinterpret_cast<uint4*>(&Asu[buf][arow][ac + 4]) = ra1;
        *reinterpret_cast<uint4*>(&Bsu[buf][brow][bc])     = rb0;
        *reinterpret_cast<uint4*>(&Bsu[buf][brow][bc + 4]) = rb1;
    };

    float c[2][8][4];
    #pragma unroll
    for (int ma = 0; ma < 2; ma++)
        #pragma unroll
        for (int nb = 0; nb < 8; nb++)
            #pragma unroll
            for (int r = 0; r < 4; r++) c[ma][nb][r] = 0.f;

    ldg(0);
    sts(0);
    __syncthreads();

    const int NIT = KD2 / KC2;   // 128
    for (int kt = 0; kt < NIT; kt++) {
        const int cur = kt & 1;
        if (kt + 1 < NIT) ldg((kt + 1) * KC2);

        #pragma unroll
        for (int ks = 0; ks < 2; ks++) {
            const int kb = ks * 8;
            unsigned a[2][4];
            #pragma unroll
            for (int ma = 0; ma < 2; ma++) {
                const int mbase = wm + ma * 16;
                a[ma][0] = Asu[cur][mbase + grp][kb + tig];
                a[ma][1] = Asu[cur][mbase + grp + 8][kb + tig];
                a[ma][2] = Asu[cur][mbase + grp][kb + tig + 4];
                a[ma][3] = Asu[cur][mbase + grp + 8][kb + tig + 4];
            }
            #pragma unroll
            for (int nb = 0; nb < 8; nb++) {
                unsigned b0 = Bsu[cur][kb + tig][wn + nb * 8 + grp];
                unsigned b1 = Bsu[cur][kb + tig + 4][wn + nb * 8 + grp];
                #pragma unroll
                for (int ma = 0; ma < 2; ma++)
                    mma_f16(c[ma][nb][0], c[ma][nb][1], c[ma][nb][2], c[ma][nb][3],
                            a[ma][0], a[ma][1], a[ma][2], a[ma][3], b0, b1);
            }
        }
        if (kt + 1 < NIT) sts(cur ^ 1);
        __syncthreads();
    }

    float* ob = out + (size_t)bb * COUT * NN;
    #pragma unroll
    for (int ma = 0; ma < 2; ma++) {
        const int m0 = wm + ma * 16 + grp;
        #pragma unroll
        for (int nb = 0; nb < 8; nb++) {
            const int col0 = wn + nb * 8 + tig * 2;
            const float bv0 = s_bias[col0], bv1 = s_bias[col0 + 1];
            ob[(size_t)col0       * NN + n0 + m0]     = c[ma][nb][0] + bv0;
            ob[(size_t)(col0 + 1) * NN + n0 + m0]     = c[ma][nb][1] + bv1;
            ob[(size_t)col0       * NN + n0 + m0 + 8] = c[ma][nb][2] + bv0;
            ob[(size_t)(col0 + 1) * NN + n0 + m0 + 8] = c[ma][nb][3] + bv1;
        }
    }
}

// ---------------- launch ----------------
extern "C" void kernel_launch(void* const* d_in, const int* in_sizes, int n_in,
                              void* d_out, int out_size) {
    const float* x       = (const float*)d_in[0];
    const float* feature = (const float*)d_in[1];
    const int*   nidx    = (const int*)  d_in[2];
    const float* Brff    = (const float*)d_in[3];
    const float* kern    = (const float*)d_in[4];
    const float* mw      = (const float*)d_in[5];
    const float* mb      = (const float*)d_in[6];
    const float* cw      = (const float*)d_in[7];
    const float* cb      = (const float*)d_in[8];
    float* out = (float*)d_out;

    prep_kernel<<<1024, 256>>>(x, feature, cw);
    point_kernel<<<NPTS, 128>>>(nidx, Brff, kern, mw, mb);
    gemm_kernel<<<NPTS / 128, 256>>>(cb, out);
}